// round 1
// baseline (speedup 1.0000x reference)
#include <cuda_runtime.h>
#include <cuda_bf16.h>
#include <math.h>

// Problem constants
#define N_TOK 16384
#define DIM   256
#define NEXP  8
#define HID   512
#define TOPK  2
#define NASSIGN (N_TOK * TOPK)   // 32768

// GEMM tiling
#define TM 128
#define KB 16
#define MAX_TILES (NASSIGN / TM + NEXP)   // 264

// ---------------- device scratch (static; no allocations) ----------------
__device__ int   g_counts[NEXP];
__device__ int   g_cursor[NEXP];
__device__ int   g_off[NEXP + 1];
__device__ int   g_ntiles;
__device__ int   g_tile_e[MAX_TILES];
__device__ int   g_tile_base[MAX_TILES];
__device__ int   g_tile_rows[MAX_TILES];

__device__ int   g_topi[NASSIGN];
__device__ float g_topw[NASSIGN];
__device__ int   g_ptok[NASSIGN];      // assignment position -> token
__device__ float g_pw[NASSIGN];        // assignment position -> routing weight
__device__ int   g_tok2pos[NASSIGN];   // (token,k) -> assignment position

__device__ float g_h[(size_t)NASSIGN * HID];   // 64 MB intermediate (post-GELU)
__device__ float g_y[(size_t)NASSIGN * DIM];   // 32 MB weighted expert outputs

// ---------------- kernel 0: init counters ----------------
__global__ void init_kernel() {
    int t = threadIdx.x;
    if (t < NEXP) { g_counts[t] = 0; g_cursor[t] = 0; }
}

// ---------------- kernel 1: gate logits + top-2 + softmax ----------------
// one warp per token
__global__ void gate_kernel(const float* __restrict__ x,
                            const float* __restrict__ Wg) {
    __shared__ float sWg[NEXP][DIM];   // transposed: sWg[e][d]
    int tid = threadIdx.x;
    for (int i = tid; i < DIM * NEXP; i += blockDim.x) {
        int e = i & (NEXP - 1);
        int d = i >> 3;
        sWg[e][d] = Wg[i];             // Wg is [D][E] row-major, i = d*8+e
    }
    __syncthreads();

    int warp = tid >> 5;
    int lane = tid & 31;
    int n = blockIdx.x * 4 + warp;
    if (n >= N_TOK) return;

    float lg[NEXP];
#pragma unroll
    for (int e = 0; e < NEXP; e++) lg[e] = 0.f;

#pragma unroll
    for (int j = 0; j < 8; j++) {
        int d = lane + 32 * j;
        float xv = x[(size_t)n * DIM + d];
#pragma unroll
        for (int e = 0; e < NEXP; e++) lg[e] += xv * sWg[e][d];
    }
#pragma unroll
    for (int e = 0; e < NEXP; e++) {
#pragma unroll
        for (int o = 16; o > 0; o >>= 1)
            lg[e] += __shfl_xor_sync(0xffffffffu, lg[e], o);
    }

    if (lane == 0) {
        // top-1
        float m1 = lg[0]; int i1 = 0;
#pragma unroll
        for (int e = 1; e < NEXP; e++) if (lg[e] > m1) { m1 = lg[e]; i1 = e; }
        // top-2
        float m2 = -1e30f; int i2 = 0;
#pragma unroll
        for (int e = 0; e < NEXP; e++)
            if (e != i1 && lg[e] > m2) { m2 = lg[e]; i2 = e; }
        // softmax over {m1, m2}; m1 >= m2
        float p2 = expf(m2 - m1);
        float inv = 1.f / (1.f + p2);
        float w1v = inv;
        float w2v = p2 * inv;
        g_topi[2 * n + 0] = i1;  g_topw[2 * n + 0] = w1v;
        g_topi[2 * n + 1] = i2;  g_topw[2 * n + 1] = w2v;
        atomicAdd(&g_counts[i1], 1);
        atomicAdd(&g_counts[i2], 1);
    }
}

// ---------------- kernel 2: offsets + tile descriptors (1 thread) ----------------
__global__ void prep_kernel() {
    int off = 0;
    for (int e = 0; e < NEXP; e++) { g_off[e] = off; off += g_counts[e]; }
    g_off[NEXP] = off;
    int t = 0;
    for (int e = 0; e < NEXP; e++) {
        int cnt = g_counts[e];
        for (int s = 0; s < cnt; s += TM) {
            g_tile_e[t]    = e;
            g_tile_base[t] = g_off[e] + s;
            g_tile_rows[t] = min(TM, cnt - s);
            t++;
        }
    }
    g_ntiles = t;
}

// ---------------- kernel 3: scatter token assignments ----------------
__global__ void scatter_kernel() {
    int idx = blockIdx.x * blockDim.x + threadIdx.x;
    if (idx >= NASSIGN) return;
    int e = g_topi[idx];
    int pos = g_off[e] + atomicAdd(&g_cursor[e], 1);
    g_ptok[pos] = idx >> 1;
    g_pw[pos]   = g_topw[idx];
    g_tok2pos[idx] = pos;
}

// ---------------- kernel 4: GEMM1 (x @ w1[e]) + bias + GELU(exact) ----------------
// grid: (MAX_TILES, HID/128); block 256 threads; C tile 128x128
__global__ void __launch_bounds__(256)
gemm1_kernel(const float* __restrict__ x,
             const float* __restrict__ w1,
             const float* __restrict__ b1) {
    int t = blockIdx.x;
    if (t >= g_ntiles) return;
    int e    = g_tile_e[t];
    int base = g_tile_base[t];
    int rows = g_tile_rows[t];
    int hbase = blockIdx.y * 128;

    __shared__ __align__(16) float As[KB][132];   // [k][row], padded
    __shared__ __align__(16) float Bs[KB][128];   // [k][col]

    int tid = threadIdx.x;
    int tx = tid & 15, ty = tid >> 4;

    // A-load assignment: 2048 elems = 512 float4; thread handles f4 idx tid (rows 0..63) and tid+256 (rows 64..127)
    int row0 = tid >> 2, f0 = tid & 3;
    int row1 = row0 + 64;
    int tok0 = (row0 < rows) ? g_ptok[base + row0] : -1;
    int tok1 = (row1 < rows) ? g_ptok[base + row1] : -1;

    const float* w1e = w1 + (size_t)e * DIM * HID;
    int kkB = tid >> 5, cg = tid & 31;   // B-load: rows kkB, kkB+8; col group cg

    float acc[8][8];
#pragma unroll
    for (int i = 0; i < 8; i++)
#pragma unroll
        for (int j = 0; j < 8; j++) acc[i][j] = 0.f;

    for (int k0 = 0; k0 < DIM; k0 += KB) {
        float4 va0 = make_float4(0.f, 0.f, 0.f, 0.f), va1 = va0;
        if (tok0 >= 0) va0 = *(const float4*)&x[(size_t)tok0 * DIM + k0 + f0 * 4];
        if (tok1 >= 0) va1 = *(const float4*)&x[(size_t)tok1 * DIM + k0 + f0 * 4];
        float4 vb0 = *(const float4*)&w1e[(size_t)(k0 + kkB) * HID + hbase + cg * 4];
        float4 vb1 = *(const float4*)&w1e[(size_t)(k0 + kkB + 8) * HID + hbase + cg * 4];
        __syncthreads();
        As[f0 * 4 + 0][row0] = va0.x; As[f0 * 4 + 1][row0] = va0.y;
        As[f0 * 4 + 2][row0] = va0.z; As[f0 * 4 + 3][row0] = va0.w;
        As[f0 * 4 + 0][row1] = va1.x; As[f0 * 4 + 1][row1] = va1.y;
        As[f0 * 4 + 2][row1] = va1.z; As[f0 * 4 + 3][row1] = va1.w;
        *(float4*)&Bs[kkB][cg * 4]     = vb0;
        *(float4*)&Bs[kkB + 8][cg * 4] = vb1;
        __syncthreads();
#pragma unroll
        for (int kk = 0; kk < KB; kk++) {
            float4 a0 = *(float4*)&As[kk][ty * 4];
            float4 a1 = *(float4*)&As[kk][64 + ty * 4];
            float4 b0 = *(float4*)&Bs[kk][tx * 4];
            float4 b1 = *(float4*)&Bs[kk][64 + tx * 4];
            float av[8] = {a0.x, a0.y, a0.z, a0.w, a1.x, a1.y, a1.z, a1.w};
            float bv[8] = {b0.x, b0.y, b0.z, b0.w, b1.x, b1.y, b1.z, b1.w};
#pragma unroll
            for (int i = 0; i < 8; i++)
#pragma unroll
                for (int j = 0; j < 8; j++) acc[i][j] += av[i] * bv[j];
        }
    }

    // epilogue: bias + exact GELU, write g_h
    const float* b1e = b1 + (size_t)e * HID;
#pragma unroll
    for (int i = 0; i < 8; i++) {
        int r = (i < 4) ? (ty * 4 + i) : (64 + ty * 4 + (i - 4));
        if (r >= rows) continue;
        size_t rowptr = (size_t)(base + r) * HID + hbase;
        float v[8];
#pragma unroll
        for (int j = 0; j < 8; j++) {
            int c = (j < 4) ? (tx * 4 + j) : (64 + tx * 4 + (j - 4));
            float z = acc[i][j] + b1e[hbase + c];
            v[j] = 0.5f * z * (1.0f + erff(z * 0.70710678118654752f));
        }
        *(float4*)&g_h[rowptr + tx * 4]      = make_float4(v[0], v[1], v[2], v[3]);
        *(float4*)&g_h[rowptr + 64 + tx * 4] = make_float4(v[4], v[5], v[6], v[7]);
    }
}

// ---------------- kernel 5: GEMM2 (h @ w2[e]) + bias + routing weight ----------------
// grid: (MAX_TILES, DIM/128); block 256 threads
__global__ void __launch_bounds__(256)
gemm2_kernel(const float* __restrict__ w2,
             const float* __restrict__ b2) {
    int t = blockIdx.x;
    if (t >= g_ntiles) return;
    int e    = g_tile_e[t];
    int base = g_tile_base[t];
    int rows = g_tile_rows[t];
    int dbase = blockIdx.y * 128;

    __shared__ __align__(16) float As[KB][132];
    __shared__ __align__(16) float Bs[KB][128];

    int tid = threadIdx.x;
    int tx = tid & 15, ty = tid >> 4;

    int row0 = tid >> 2, f0 = tid & 3;
    int row1 = row0 + 64;
    bool ok0 = (row0 < rows), ok1 = (row1 < rows);

    const float* w2e = w2 + (size_t)e * HID * DIM;
    int kkB = tid >> 5, cg = tid & 31;

    float acc[8][8];
#pragma unroll
    for (int i = 0; i < 8; i++)
#pragma unroll
        for (int j = 0; j < 8; j++) acc[i][j] = 0.f;

    for (int k0 = 0; k0 < HID; k0 += KB) {
        float4 va0 = make_float4(0.f, 0.f, 0.f, 0.f), va1 = va0;
        if (ok0) va0 = *(const float4*)&g_h[(size_t)(base + row0) * HID + k0 + f0 * 4];
        if (ok1) va1 = *(const float4*)&g_h[(size_t)(base + row1) * HID + k0 + f0 * 4];
        float4 vb0 = *(const float4*)&w2e[(size_t)(k0 + kkB) * DIM + dbase + cg * 4];
        float4 vb1 = *(const float4*)&w2e[(size_t)(k0 + kkB + 8) * DIM + dbase + cg * 4];
        __syncthreads();
        As[f0 * 4 + 0][row0] = va0.x; As[f0 * 4 + 1][row0] = va0.y;
        As[f0 * 4 + 2][row0] = va0.z; As[f0 * 4 + 3][row0] = va0.w;
        As[f0 * 4 + 0][row1] = va1.x; As[f0 * 4 + 1][row1] = va1.y;
        As[f0 * 4 + 2][row1] = va1.z; As[f0 * 4 + 3][row1] = va1.w;
        *(float4*)&Bs[kkB][cg * 4]     = vb0;
        *(float4*)&Bs[kkB + 8][cg * 4] = vb1;
        __syncthreads();
#pragma unroll
        for (int kk = 0; kk < KB; kk++) {
            float4 a0 = *(float4*)&As[kk][ty * 4];
            float4 a1 = *(float4*)&As[kk][64 + ty * 4];
            float4 b0 = *(float4*)&Bs[kk][tx * 4];
            float4 b1 = *(float4*)&Bs[kk][64 + tx * 4];
            float av[8] = {a0.x, a0.y, a0.z, a0.w, a1.x, a1.y, a1.z, a1.w};
            float bv[8] = {b0.x, b0.y, b0.z, b0.w, b1.x, b1.y, b1.z, b1.w};
#pragma unroll
            for (int i = 0; i < 8; i++)
#pragma unroll
                for (int j = 0; j < 8; j++) acc[i][j] += av[i] * bv[j];
        }
    }

    const float* b2e = b2 + (size_t)e * DIM;
#pragma unroll
    for (int i = 0; i < 8; i++) {
        int r = (i < 4) ? (ty * 4 + i) : (64 + ty * 4 + (i - 4));
        if (r >= rows) continue;
        float wgt = g_pw[base + r];
        size_t rowptr = (size_t)(base + r) * DIM + dbase;
        float v[8];
#pragma unroll
        for (int j = 0; j < 8; j++) {
            int c = (j < 4) ? (tx * 4 + j) : (64 + tx * 4 + (j - 4));
            v[j] = (acc[i][j] + b2e[dbase + c]) * wgt;
        }
        *(float4*)&g_y[rowptr + tx * 4]      = make_float4(v[0], v[1], v[2], v[3]);
        *(float4*)&g_y[rowptr + 64 + tx * 4] = make_float4(v[4], v[5], v[6], v[7]);
    }
}

// ---------------- kernel 6: deterministic combine ----------------
__global__ void combine_kernel(float* __restrict__ out) {
    int idx = blockIdx.x * blockDim.x + threadIdx.x;  // over N*64 float4s
    if (idx >= N_TOK * (DIM / 4)) return;
    int n = idx >> 6;
    int q = idx & 63;
    int p0 = g_tok2pos[2 * n + 0];
    int p1 = g_tok2pos[2 * n + 1];
    const float4* y0 = (const float4*)&g_y[(size_t)p0 * DIM];
    const float4* y1 = (const float4*)&g_y[(size_t)p1 * DIM];
    float4 a = y0[q];
    float4 b = y1[q];
    float4 r = make_float4(a.x + b.x, a.y + b.y, a.z + b.z, a.w + b.w);
    ((float4*)out)[(size_t)n * 64 + q] = r;
}

// ---------------- launch ----------------
extern "C" void kernel_launch(void* const* d_in, const int* in_sizes, int n_in,
                              void* d_out, int out_size) {
    const float* x  = (const float*)d_in[0];   // [N, D]
    const float* Wg = (const float*)d_in[1];   // [D, E]
    const float* w1 = (const float*)d_in[2];   // [E, D, H]
    const float* b1 = (const float*)d_in[3];   // [E, H]
    const float* w2 = (const float*)d_in[4];   // [E, H, D]
    const float* b2 = (const float*)d_in[5];   // [E, D]
    float* out = (float*)d_out;                // [N, D]

    init_kernel<<<1, 32>>>();
    gate_kernel<<<N_TOK / 4, 128>>>(x, Wg);
    prep_kernel<<<1, 1>>>();
    scatter_kernel<<<NASSIGN / 256, 256>>>();
    gemm1_kernel<<<dim3(MAX_TILES, HID / 128), 256>>>(x, w1, b1);
    gemm2_kernel<<<dim3(MAX_TILES, DIM / 128), 256>>>(w2, b2);
    combine_kernel<<<(N_TOK * (DIM / 4)) / 256, 256>>>(out);
}

// round 8
// speedup vs baseline: 1.0709x; 1.0709x over previous
#include <cuda_runtime.h>
#include <cuda_bf16.h>
#include <math.h>
#include <stdint.h>

// Problem constants
#define N_TOK 16384
#define DIM   256
#define NEXP  8
#define HID   512
#define TOPK  2
#define NASSIGN (N_TOK * TOPK)   // 32768

// GEMM tiling
#define TM 128
#define KB 16
#define MAX_TILES (NASSIGN / TM + NEXP)   // 264

// ---------------- packed f32x2 helpers ----------------
__device__ __forceinline__ unsigned long long pack_dup(float a) {
    unsigned long long r;
    asm("mov.b64 %0, {%1, %1};" : "=l"(r) : "f"(a));
    return r;
}
__device__ __forceinline__ void fma_x2(unsigned long long& c, unsigned long long a,
                                       unsigned long long b) {
    asm("fma.rn.f32x2 %0, %1, %2, %0;" : "+l"(c) : "l"(a), "l"(b));
}
__device__ __forceinline__ float2 unpack2(unsigned long long v) {
    float2 r;
    asm("mov.b64 {%0, %1}, %2;" : "=f"(r.x), "=f"(r.y) : "l"(v));
    return r;
}

// ---------------- device scratch (static; no allocations) ----------------
__device__ int   g_counts[NEXP];
__device__ int   g_cursor[NEXP];
__device__ int   g_off[NEXP + 1];
__device__ int   g_ntiles;
__device__ int   g_tile_e[MAX_TILES];
__device__ int   g_tile_base[MAX_TILES];
__device__ int   g_tile_rows[MAX_TILES];

__device__ int   g_topi[NASSIGN];
__device__ float g_topw[NASSIGN];
__device__ int   g_ptok[NASSIGN];      // assignment position -> token
__device__ float g_pw[NASSIGN];        // assignment position -> routing weight
__device__ int   g_tok2pos[NASSIGN];   // (token,k) -> assignment position

__device__ float g_h[(size_t)NASSIGN * HID];   // 64 MB intermediate (post-GELU)
__device__ float g_y[(size_t)NASSIGN * DIM];   // 32 MB weighted expert outputs

// ---------------- kernel 0: init counters ----------------
__global__ void init_kernel() {
    int t = threadIdx.x;
    if (t < NEXP) { g_counts[t] = 0; g_cursor[t] = 0; }
}

// ---------------- kernel 1: gate logits + top-2 + softmax ----------------
// one warp per token
__global__ void gate_kernel(const float* __restrict__ x,
                            const float* __restrict__ Wg) {
    __shared__ float sWg[NEXP][DIM];   // transposed: sWg[e][d]
    int tid = threadIdx.x;
    for (int i = tid; i < DIM * NEXP; i += blockDim.x) {
        int e = i & (NEXP - 1);
        int d = i >> 3;
        sWg[e][d] = Wg[i];             // Wg is [D][E] row-major, i = d*8+e
    }
    __syncthreads();

    int warp = tid >> 5;
    int lane = tid & 31;
    int n = blockIdx.x * 4 + warp;
    if (n >= N_TOK) return;

    float lg[NEXP];
#pragma unroll
    for (int e = 0; e < NEXP; e++) lg[e] = 0.f;

#pragma unroll
    for (int j = 0; j < 8; j++) {
        int d = lane + 32 * j;
        float xv = x[(size_t)n * DIM + d];
#pragma unroll
        for (int e = 0; e < NEXP; e++) lg[e] += xv * sWg[e][d];
    }
#pragma unroll
    for (int e = 0; e < NEXP; e++) {
#pragma unroll
        for (int o = 16; o > 0; o >>= 1)
            lg[e] += __shfl_xor_sync(0xffffffffu, lg[e], o);
    }

    if (lane == 0) {
        float m1 = lg[0]; int i1 = 0;
#pragma unroll
        for (int e = 1; e < NEXP; e++) if (lg[e] > m1) { m1 = lg[e]; i1 = e; }
        float m2 = -1e30f; int i2 = 0;
#pragma unroll
        for (int e = 0; e < NEXP; e++)
            if (e != i1 && lg[e] > m2) { m2 = lg[e]; i2 = e; }
        float p2 = expf(m2 - m1);
        float inv = 1.f / (1.f + p2);
        float w1v = inv;
        float w2v = p2 * inv;
        g_topi[2 * n + 0] = i1;  g_topw[2 * n + 0] = w1v;
        g_topi[2 * n + 1] = i2;  g_topw[2 * n + 1] = w2v;
        atomicAdd(&g_counts[i1], 1);
        atomicAdd(&g_counts[i2], 1);
    }
}

// ---------------- kernel 2: offsets + tile descriptors (1 thread) ----------------
__global__ void prep_kernel() {
    int off = 0;
    for (int e = 0; e < NEXP; e++) { g_off[e] = off; off += g_counts[e]; }
    g_off[NEXP] = off;
    int t = 0;
    for (int e = 0; e < NEXP; e++) {
        int cnt = g_counts[e];
        for (int s = 0; s < cnt; s += TM) {
            g_tile_e[t]    = e;
            g_tile_base[t] = g_off[e] + s;
            g_tile_rows[t] = min(TM, cnt - s);
            t++;
        }
    }
    g_ntiles = t;
}

// ---------------- kernel 3: scatter token assignments ----------------
__global__ void scatter_kernel() {
    int idx = blockIdx.x * blockDim.x + threadIdx.x;
    if (idx >= NASSIGN) return;
    int e = g_topi[idx];
    int pos = g_off[e] + atomicAdd(&g_cursor[e], 1);
    g_ptok[pos] = idx >> 1;
    g_pw[pos]   = g_topw[idx];
    g_tok2pos[idx] = pos;
}

// ---------------- kernel 4: GEMM1 (x @ w1[e]) + bias + GELU(exact) ----------------
// grid: (MAX_TILES, HID/128); block 256 threads; C tile 128x128
__global__ void __launch_bounds__(256)
gemm1_kernel(const float* __restrict__ x,
             const float* __restrict__ w1,
             const float* __restrict__ b1) {
    int t = blockIdx.x;
    if (t >= g_ntiles) return;
    int e    = g_tile_e[t];
    int base = g_tile_base[t];
    int rows = g_tile_rows[t];
    int hbase = blockIdx.y * 128;

    __shared__ __align__(16) float As[KB][132];   // [k][row], padded
    __shared__ __align__(16) float Bs[KB][128];   // [k][col]

    int tid = threadIdx.x;
    int tx = tid & 15, ty = tid >> 4;

    int row0 = tid >> 2, f0 = tid & 3;
    int row1 = row0 + 64;
    int tok0 = (row0 < rows) ? g_ptok[base + row0] : -1;
    int tok1 = (row1 < rows) ? g_ptok[base + row1] : -1;

    const float* w1e = w1 + (size_t)e * DIM * HID;
    int kkB = tid >> 5, cg = tid & 31;   // B-load: rows kkB, kkB+8; col group cg

    unsigned long long acc[8][4];        // 8 rows x 4 col-pairs (f32x2)
#pragma unroll
    for (int i = 0; i < 8; i++)
#pragma unroll
        for (int j = 0; j < 4; j++) acc[i][j] = 0ULL;

    for (int k0 = 0; k0 < DIM; k0 += KB) {
        float4 va0 = make_float4(0.f, 0.f, 0.f, 0.f), va1 = va0;
        if (tok0 >= 0) va0 = *(const float4*)&x[(size_t)tok0 * DIM + k0 + f0 * 4];
        if (tok1 >= 0) va1 = *(const float4*)&x[(size_t)tok1 * DIM + k0 + f0 * 4];
        float4 vb0 = *(const float4*)&w1e[(size_t)(k0 + kkB) * HID + hbase + cg * 4];
        float4 vb1 = *(const float4*)&w1e[(size_t)(k0 + kkB + 8) * HID + hbase + cg * 4];
        __syncthreads();
        As[f0 * 4 + 0][row0] = va0.x; As[f0 * 4 + 1][row0] = va0.y;
        As[f0 * 4 + 2][row0] = va0.z; As[f0 * 4 + 3][row0] = va0.w;
        As[f0 * 4 + 0][row1] = va1.x; As[f0 * 4 + 1][row1] = va1.y;
        As[f0 * 4 + 2][row1] = va1.z; As[f0 * 4 + 3][row1] = va1.w;
        *(float4*)&Bs[kkB][cg * 4]     = vb0;
        *(float4*)&Bs[kkB + 8][cg * 4] = vb1;
        __syncthreads();
#pragma unroll
        for (int kk = 0; kk < KB; kk++) {
            float4 a0 = *(float4*)&As[kk][ty * 4];
            float4 a1 = *(float4*)&As[kk][64 + ty * 4];
            // b pairs straight from 128-bit smem loads
            unsigned long long bp[4];
            {
                float4 b0 = *(float4*)&Bs[kk][tx * 4];
                float4 b1v = *(float4*)&Bs[kk][64 + tx * 4];
                unsigned long long* p0 = (unsigned long long*)&b0;
                unsigned long long* p1 = (unsigned long long*)&b1v;
                bp[0] = p0[0]; bp[1] = p0[1]; bp[2] = p1[0]; bp[3] = p1[1];
            }
            float av[8] = {a0.x, a0.y, a0.z, a0.w, a1.x, a1.y, a1.z, a1.w};
#pragma unroll
            for (int i = 0; i < 8; i++) {
                unsigned long long aa = pack_dup(av[i]);
#pragma unroll
                for (int j = 0; j < 4; j++) fma_x2(acc[i][j], aa, bp[j]);
            }
        }
    }

    // epilogue: bias + exact GELU, write g_h
    const float* b1e = b1 + (size_t)e * HID;
#pragma unroll
    for (int i = 0; i < 8; i++) {
        int r = (i < 4) ? (ty * 4 + i) : (64 + ty * 4 + (i - 4));
        if (r >= rows) continue;
        size_t rowptr = (size_t)(base + r) * HID + hbase;
        float v[8];
#pragma unroll
        for (int jp = 0; jp < 4; jp++) {
            float2 p = unpack2(acc[i][jp]);
            v[2 * jp]     = p.x;
            v[2 * jp + 1] = p.y;
        }
#pragma unroll
        for (int j = 0; j < 8; j++) {
            int c = (j < 4) ? (tx * 4 + j) : (64 + tx * 4 + (j - 4));
            float z = v[j] + b1e[hbase + c];
            v[j] = 0.5f * z * (1.0f + erff(z * 0.70710678118654752f));
        }
        *(float4*)&g_h[rowptr + tx * 4]      = make_float4(v[0], v[1], v[2], v[3]);
        *(float4*)&g_h[rowptr + 64 + tx * 4] = make_float4(v[4], v[5], v[6], v[7]);
    }
}

// ---------------- kernel 5: GEMM2 (h @ w2[e]) + bias + routing weight ----------------
// grid: (MAX_TILES, DIM/128); block 256 threads
__global__ void __launch_bounds__(256)
gemm2_kernel(const float* __restrict__ w2,
             const float* __restrict__ b2) {
    int t = blockIdx.x;
    if (t >= g_ntiles) return;
    int e    = g_tile_e[t];
    int base = g_tile_base[t];
    int rows = g_tile_rows[t];
    int dbase = blockIdx.y * 128;

    __shared__ __align__(16) float As[KB][132];
    __shared__ __align__(16) float Bs[KB][128];

    int tid = threadIdx.x;
    int tx = tid & 15, ty = tid >> 4;

    int row0 = tid >> 2, f0 = tid & 3;
    int row1 = row0 + 64;
    bool ok0 = (row0 < rows), ok1 = (row1 < rows);

    const float* w2e = w2 + (size_t)e * HID * DIM;
    int kkB = tid >> 5, cg = tid & 31;

    unsigned long long acc[8][4];
#pragma unroll
    for (int i = 0; i < 8; i++)
#pragma unroll
        for (int j = 0; j < 4; j++) acc[i][j] = 0ULL;

    for (int k0 = 0; k0 < HID; k0 += KB) {
        float4 va0 = make_float4(0.f, 0.f, 0.f, 0.f), va1 = va0;
        if (ok0) va0 = *(const float4*)&g_h[(size_t)(base + row0) * HID + k0 + f0 * 4];
        if (ok1) va1 = *(const float4*)&g_h[(size_t)(base + row1) * HID + k0 + f0 * 4];
        float4 vb0 = *(const float4*)&w2e[(size_t)(k0 + kkB) * DIM + dbase + cg * 4];
        float4 vb1 = *(const float4*)&w2e[(size_t)(k0 + kkB + 8) * DIM + dbase + cg * 4];
        __syncthreads();
        As[f0 * 4 + 0][row0] = va0.x; As[f0 * 4 + 1][row0] = va0.y;
        As[f0 * 4 + 2][row0] = va0.z; As[f0 * 4 + 3][row0] = va0.w;
        As[f0 * 4 + 0][row1] = va1.x; As[f0 * 4 + 1][row1] = va1.y;
        As[f0 * 4 + 2][row1] = va1.z; As[f0 * 4 + 3][row1] = va1.w;
        *(float4*)&Bs[kkB][cg * 4]     = vb0;
        *(float4*)&Bs[kkB + 8][cg * 4] = vb1;
        __syncthreads();
#pragma unroll
        for (int kk = 0; kk < KB; kk++) {
            float4 a0 = *(float4*)&As[kk][ty * 4];
            float4 a1 = *(float4*)&As[kk][64 + ty * 4];
            unsigned long long bp[4];
            {
                float4 b0 = *(float4*)&Bs[kk][tx * 4];
                float4 b1v = *(float4*)&Bs[kk][64 + tx * 4];
                unsigned long long* p0 = (unsigned long long*)&b0;
                unsigned long long* p1 = (unsigned long long*)&b1v;
                bp[0] = p0[0]; bp[1] = p0[1]; bp[2] = p1[0]; bp[3] = p1[1];
            }
            float av[8] = {a0.x, a0.y, a0.z, a0.w, a1.x, a1.y, a1.z, a1.w};
#pragma unroll
            for (int i = 0; i < 8; i++) {
                unsigned long long aa = pack_dup(av[i]);
#pragma unroll
                for (int j = 0; j < 4; j++) fma_x2(acc[i][j], aa, bp[j]);
            }
        }
    }

    const float* b2e = b2 + (size_t)e * DIM;
#pragma unroll
    for (int i = 0; i < 8; i++) {
        int r = (i < 4) ? (ty * 4 + i) : (64 + ty * 4 + (i - 4));
        if (r >= rows) continue;
        float wgt = g_pw[base + r];
        size_t rowptr = (size_t)(base + r) * DIM + dbase;
        float v[8];
#pragma unroll
        for (int jp = 0; jp < 4; jp++) {
            float2 p = unpack2(acc[i][jp]);
            v[2 * jp]     = p.x;
            v[2 * jp + 1] = p.y;
        }
#pragma unroll
        for (int j = 0; j < 8; j++) {
            int c = (j < 4) ? (tx * 4 + j) : (64 + tx * 4 + (j - 4));
            v[j] = (v[j] + b2e[dbase + c]) * wgt;
        }
        *(float4*)&g_y[rowptr + tx * 4]      = make_float4(v[0], v[1], v[2], v[3]);
        *(float4*)&g_y[rowptr + 64 + tx * 4] = make_float4(v[4], v[5], v[6], v[7]);
    }
}

// ---------------- kernel 6: deterministic combine ----------------
__global__ void combine_kernel(float* __restrict__ out) {
    int idx = blockIdx.x * blockDim.x + threadIdx.x;  // over N*64 float4s
    if (idx >= N_TOK * (DIM / 4)) return;
    int n = idx >> 6;
    int q = idx & 63;
    int p0 = g_tok2pos[2 * n + 0];
    int p1 = g_tok2pos[2 * n + 1];
    const float4* y0 = (const float4*)&g_y[(size_t)p0 * DIM];
    const float4* y1 = (const float4*)&g_y[(size_t)p1 * DIM];
    float4 a = y0[q];
    float4 b = y1[q];
    float4 r = make_float4(a.x + b.x, a.y + b.y, a.z + b.z, a.w + b.w);
    ((float4*)out)[(size_t)n * 64 + q] = r;
}

// ---------------- launch ----------------
extern "C" void kernel_launch(void* const* d_in, const int* in_sizes, int n_in,
                              void* d_out, int out_size) {
    const float* x  = (const float*)d_in[0];   // [N, D]
    const float* Wg = (const float*)d_in[1];   // [D, E]
    const float* w1 = (const float*)d_in[2];   // [E, D, H]
    const float* b1 = (const float*)d_in[3];   // [E, H]
    const float* w2 = (const float*)d_in[4];   // [E, H, D]
    const float* b2 = (const float*)d_in[5];   // [E, D]
    float* out = (float*)d_out;                // [N, D]

    init_kernel<<<1, 32>>>();
    gate_kernel<<<N_TOK / 4, 128>>>(x, Wg);
    prep_kernel<<<1, 1>>>();
    scatter_kernel<<<NASSIGN / 256, 256>>>();
    gemm1_kernel<<<dim3(MAX_TILES, HID / 128), 256>>>(x, w1, b1);
    gemm2_kernel<<<dim3(MAX_TILES, DIM / 128), 256>>>(w2, b2);
    combine_kernel<<<(N_TOK * (DIM / 4)) / 256, 256>>>(out);
}